// round 14
// baseline (speedup 1.0000x reference)
#include <cuda_runtime.h>
#include <cuda_fp16.h>
#include <cstdint>

// ---------------- problem constants ----------------
#define NV 32768
#define NC 8192
#define DIM 64
#define Q_ELEMS (NV * DIM)
#define OFF_VQ Q_ELEMS
#define OFF_COMMIT (Q_ELEMS + 1)
#define OFF_IDX (Q_ELEMS + 2)

#define KP_BYTES 144
#define TILE_M 128
#define TILE_N 64
#define NT (NC / TILE_N)        // 128
#define M_BLOCKS (NV / TILE_M)  // 256
#define TAU 0.15f               // ~23-sigma statistical cover of fp16 score error

#define SM_A 0
#define SM_B 18432
#define SM_BSTRIDE 9472
#define SM_ESQ_OFF 9216
#define DYN_SMEM (18432 + 3 * 9472)

#define QBLOCKS (NV / 64)       // 512

// ---------------- device scratch ----------------
__device__ __align__(16) __half g_eh[NC * DIM];
__device__ __align__(16) float4 g_eT4[16 * NC];
__device__ __align__(16) float g_esq[NC];
__device__ int g_bidx[NV];
__device__ int3 g_pair[NV];
__device__ int g_full[NV];
__device__ int g_npair;
__device__ int g_nfull;
__device__ float g_partial[QBLOCKS];
__device__ int g_qticket;

// ---------------- PTX helpers ----------------
__device__ __forceinline__ uint32_t smem_u32(const void* p) {
    uint32_t a;
    asm("{ .reg .u64 t; cvta.to.shared.u64 t, %1; cvt.u32.u64 %0, t; }" : "=r"(a) : "l"(p));
    return a;
}
__device__ __forceinline__ void cpa16(uint32_t dst, const void* src) {
    asm volatile("cp.async.cg.shared.global [%0], [%1], 16;" :: "r"(dst), "l"(src));
}
#define CP_COMMIT() asm volatile("cp.async.commit_group;" ::: "memory")
#define CP_WAIT(n) asm volatile("cp.async.wait_group %0;" :: "n"(n) : "memory")

__device__ __forceinline__ void ldsm4(uint32_t& r0, uint32_t& r1, uint32_t& r2,
                                      uint32_t& r3, uint32_t addr) {
    asm volatile("ldmatrix.sync.aligned.m8n8.x4.shared.b16 {%0,%1,%2,%3}, [%4];"
                 : "=r"(r0), "=r"(r1), "=r"(r2), "=r"(r3) : "r"(addr));
}
__device__ __forceinline__ void mma16816(float* c, const uint32_t* a, uint32_t b0,
                                         uint32_t b1) {
    asm volatile(
        "mma.sync.aligned.m16n8k16.row.col.f32.f16.f16.f32 "
        "{%0,%1,%2,%3}, {%4,%5,%6,%7}, {%8,%9}, {%0,%1,%2,%3};"
        : "+f"(c[0]), "+f"(c[1]), "+f"(c[2]), "+f"(c[3])
        : "r"(a[0]), "r"(a[1]), "r"(a[2]), "r"(a[3]), "r"(b0), "r"(b1));
}

__device__ __forceinline__ void merge3(float& b1, float& b2, float& b3, int& i1, int& i2,
                                       float c1, float c2, float c3, int j1, int j2) {
    if (c1 < b1 || (c1 == b1 && j1 < i1)) {
        float t; int ti;
        t = b1; b1 = c1; c1 = t; ti = i1; i1 = j1; j1 = ti;
        t = b2; b2 = c2; c2 = t; ti = i2; i2 = j2; j2 = ti;
        t = b3; b3 = c3; c3 = t;
    }
    if (c1 < b2 || (c1 == b2 && j1 < i2)) {
        b3 = fminf(b2, c2);
        b2 = c1; i2 = j1;
    } else {
        b3 = fminf(b3, c1);
    }
}

// ---------------- prep: codebook ----------------
__global__ void prep_emb_kernel(const float* __restrict__ emb) {
    int c = blockIdx.x * blockDim.x + threadIdx.x;
    if (c == 0) { g_npair = 0; g_nfull = 0; g_qticket = 0; }
    if (c >= NC) return;
    const float4* row = reinterpret_cast<const float4*>(emb + (size_t)c * DIM);
    __half2* dst = reinterpret_cast<__half2*>(g_eh + (size_t)c * DIM);
    float s = 0.f;
#pragma unroll
    for (int i = 0; i < 16; i++) {
        float4 v = row[i];
        s += v.x * v.x + v.y * v.y + v.z * v.z + v.w * v.w;
        dst[2 * i] = __halves2half2(__float2half_rn(v.x), __float2half_rn(v.y));
        dst[2 * i + 1] = __halves2half2(__float2half_rn(v.z), __float2half_rn(v.w));
        g_eT4[i * NC + c] = v;
    }
    g_esq[c] = s;
}

// ---------------- main: HMMA distance GEMM + top-3 argmin (frozen since R9) ----------------
__global__ void __launch_bounds__(256, 2) vq_mma_kernel(const float* __restrict__ z) {
    extern __shared__ __align__(16) char dsm[];
    __shared__ float s_b[2][TILE_M], s_b2[2][TILE_M], s_b3[2][TILE_M];
    __shared__ int s_i[2][TILE_M], s_i2[2][TILE_M];

    const int tid = threadIdx.x;
    const int lane = tid & 31, wid = tid >> 5;
    const int wm = wid & 3, wn = wid >> 2;
    const uint32_t sb = smem_u32(dsm);

    {
        const float4* asrc =
            reinterpret_cast<const float4*>(z + (size_t)blockIdx.x * TILE_M * DIM);
#pragma unroll
        for (int k = 0; k < 4; k++) {
            int ch = tid + k * 256;
            int r = ch >> 3, pc = ch & 7;
            float4 f0 = asrc[2 * ch], f1 = asrc[2 * ch + 1];
            __half2 h[4];
            h[0] = __floats2half2_rn(f0.x, f0.y);
            h[1] = __floats2half2_rn(f0.z, f0.w);
            h[2] = __floats2half2_rn(f1.x, f1.y);
            h[3] = __floats2half2_rn(f1.z, f1.w);
            *reinterpret_cast<uint4*>(dsm + SM_A + r * KP_BYTES + pc * 16) =
                *reinterpret_cast<uint4*>(h);
        }
    }

    auto loadB = [&](int t, int stg) {
        uint32_t Bs = sb + SM_B + stg * SM_BSTRIDE;
        const uint4* bsrc =
            reinterpret_cast<const uint4*>(g_eh + (size_t)t * TILE_N * DIM);
#pragma unroll
        for (int i = 0; i < 2; i++) {
            int ch = tid + i * 256;
            int r = ch >> 3, c = ch & 7;
            cpa16(Bs + r * KP_BYTES + c * 16, bsrc + ch);
        }
        if (tid < 16)
            cpa16(Bs + SM_ESQ_OFF + tid * 16,
                  reinterpret_cast<const uint4*>(g_esq + t * TILE_N) + tid);
    };
    loadB(0, 0);
    CP_COMMIT();
    loadB(1, 1);
    CP_COMMIT();

    float b1[4], b2[4], b3[4];
    int i1[4], i2[4];
#pragma unroll
    for (int s = 0; s < 4; s++) {
        b1[s] = 3.4e38f; b2[s] = 3.4e38f; b3[s] = 3.4e38f; i1[s] = 0; i2[s] = 0;
    }

    const uint32_t a_row = wm * 32 + (lane & 15);
    const uint32_t a_koff = (lane >> 4) * 8;
    const uint32_t b_row0 = wn * 32 + ((lane >> 4) * 8) + (lane & 7);
    const uint32_t b_koff = ((lane >> 3) & 1) * 8;
    const int nq = (lane & 3) * 2;

    int st = 0, st2 = 2;
    for (int t = 0; t < NT; t++) {
        if (t + 1 < NT) { CP_WAIT(1); }
        else            { CP_WAIT(0); }
        __syncthreads();
        if (t + 2 < NT) { loadB(t + 2, st2); CP_COMMIT(); }

        float acc[2][4][4];
#pragma unroll
        for (int mf = 0; mf < 2; mf++)
#pragma unroll
            for (int nf = 0; nf < 4; nf++)
#pragma unroll
                for (int e = 0; e < 4; e++) acc[mf][nf][e] = 0.f;

        const uint32_t Bs = sb + SM_B + st * SM_BSTRIDE;
#pragma unroll
        for (int ks = 0; ks < DIM / 16; ks++) {
            uint32_t a[2][4];
#pragma unroll
            for (int mf = 0; mf < 2; mf++)
                ldsm4(a[mf][0], a[mf][1], a[mf][2], a[mf][3],
                      sb + SM_A + (a_row + mf * 16) * KP_BYTES +
                          (ks * 16 + a_koff) * 2);
            uint32_t b[4][2];
#pragma unroll
            for (int nh = 0; nh < 2; nh++)
                ldsm4(b[2 * nh][0], b[2 * nh][1], b[2 * nh + 1][0], b[2 * nh + 1][1],
                      Bs + (b_row0 + nh * 16) * KP_BYTES + (ks * 16 + b_koff) * 2);
#pragma unroll
            for (int mf = 0; mf < 2; mf++)
#pragma unroll
                for (int nf = 0; nf < 4; nf++)
                    mma16816(acc[mf][nf], a[mf], b[nf][0], b[nf][1]);
        }

        const float* esq =
            reinterpret_cast<const float*>(dsm + SM_B + st * SM_BSTRIDE + SM_ESQ_OFF);
        float sc[4][8];
#pragma unroll
        for (int mf = 0; mf < 2; mf++) {
#pragma unroll
            for (int nf = 0; nf < 4; nf++) {
                const int n0 = wn * 32 + nf * 8 + nq;
                const float e0 = esq[n0], e1 = esq[n0 + 1];
#pragma unroll
                for (int h = 0; h < 2; h++) {
                    sc[mf * 2 + h][nf * 2 + 0] = fmaf(-2.f, acc[mf][nf][2 * h], e0);
                    sc[mf * 2 + h][nf * 2 + 1] = fmaf(-2.f, acc[mf][nf][2 * h + 1], e1);
                }
            }
        }
#pragma unroll
        for (int s = 0; s < 4; s++) {
            float m01 = fminf(sc[s][0], sc[s][1]);
            float m23 = fminf(sc[s][2], sc[s][3]);
            float m45 = fminf(sc[s][4], sc[s][5]);
            float m67 = fminf(sc[s][6], sc[s][7]);
            float tmin = fminf(fminf(m01, m23), fminf(m45, m67));
            if (tmin < b3[s]) {
#pragma unroll
                for (int k = 0; k < 8; k++) {
                    float v = sc[s][k];
                    int idx = t * TILE_N + wn * 32 + (k >> 1) * 8 + nq + (k & 1);
                    if (v < b1[s]) {
                        b3[s] = b2[s]; b2[s] = b1[s]; i2[s] = i1[s];
                        b1[s] = v; i1[s] = idx;
                    } else if (v < b2[s]) {
                        b3[s] = b2[s]; b2[s] = v; i2[s] = idx;
                    } else if (v < b3[s]) {
                        b3[s] = v;
                    }
                }
            }
        }
        st = (st == 2) ? 0 : st + 1;
        st2 = (st2 == 2) ? 0 : st2 + 1;
    }

#pragma unroll
    for (int o = 1; o < 4; o <<= 1) {
#pragma unroll
        for (int s = 0; s < 4; s++) {
            float c1 = __shfl_xor_sync(0xffffffffu, b1[s], o);
            float c2 = __shfl_xor_sync(0xffffffffu, b2[s], o);
            float c3 = __shfl_xor_sync(0xffffffffu, b3[s], o);
            int j1 = __shfl_xor_sync(0xffffffffu, i1[s], o);
            int j2 = __shfl_xor_sync(0xffffffffu, i2[s], o);
            merge3(b1[s], b2[s], b3[s], i1[s], i2[s], c1, c2, c3, j1, j2);
        }
    }
    if ((lane & 3) == 0) {
#pragma unroll
        for (int s = 0; s < 4; s++) {
            int row = wm * 32 + (s >> 1) * 16 + (lane >> 2) + (s & 1) * 8;
            s_b[wn][row] = b1[s];
            s_b2[wn][row] = b2[s];
            s_b3[wn][row] = b3[s];
            s_i[wn][row] = i1[s];
            s_i2[wn][row] = i2[s];
        }
    }
    __syncthreads();
    if (tid < TILE_M) {
        float B1 = s_b[0][tid], B2 = s_b2[0][tid], B3 = s_b3[0][tid];
        int I1 = s_i[0][tid], I2 = s_i2[0][tid];
        merge3(B1, B2, B3, I1, I2,
               s_b[1][tid], s_b2[1][tid], s_b3[1][tid], s_i[1][tid], s_i2[1][tid]);
        const int v = blockIdx.x * TILE_M + tid;
        if (B2 - B1 >= TAU) {
            g_bidx[v] = I1;
        } else if (B3 - B1 >= TAU) {
            int p = atomicAdd(&g_npair, 1);
            g_pair[p] = make_int3(v, I1, I2);
        } else {
            int p = atomicAdd(&g_nfull, 1);
            g_full[p] = v;
        }
    }
}

// ---------------- combined fixup: pairs (threads) then full rescan (4 voxels/block) ----------------
__global__ void __launch_bounds__(256, 2) fixup_kernel(const float* __restrict__ z,
                                                       const float* __restrict__ emb) {
    // ---- phase 1: pair fixup ----
    {
        const int n = g_npair;
        const int stride = gridDim.x * blockDim.x;
        for (int i = blockIdx.x * blockDim.x + threadIdx.x; i < n; i += stride) {
            int3 p = g_pair[i];
            const float4* zp = reinterpret_cast<const float4*>(z + (size_t)p.x * DIM);
            const float4* e1 = reinterpret_cast<const float4*>(emb + (size_t)p.y * DIM);
            const float4* e2 = reinterpret_cast<const float4*>(emb + (size_t)p.z * DIM);
            float d1 = 0.f, d2 = 0.f;
#pragma unroll
            for (int j = 0; j < 16; j++) {
                float4 zv = zp[j];
                float4 ea = e1[j], eb = e2[j];
                d1 = fmaf(zv.x, ea.x, d1); d1 = fmaf(zv.y, ea.y, d1);
                d1 = fmaf(zv.z, ea.z, d1); d1 = fmaf(zv.w, ea.w, d1);
                d2 = fmaf(zv.x, eb.x, d2); d2 = fmaf(zv.y, eb.y, d2);
                d2 = fmaf(zv.z, eb.z, d2); d2 = fmaf(zv.w, eb.w, d2);
            }
            float s1 = fmaf(-2.f, d1, g_esq[p.y]);
            float s2 = fmaf(-2.f, d2, g_esq[p.z]);
            int win;
            if (s1 < s2) win = p.y;
            else if (s2 < s1) win = p.z;
            else win = min(p.y, p.z);
            g_bidx[p.x] = win;
        }
    }

    // ---- phase 2: full rescan, 4 voxels per block ----
    __shared__ __align__(16) float4 s_z4[4][16];
    __shared__ float s_v[4][256];
    __shared__ int s_ix[4][256];
    const int tid = threadIdx.x;
    const int nflag = g_nfull;

    for (int i = blockIdx.x * 4; i < nflag; i += gridDim.x * 4) {
        int vs[4];
#pragma unroll
        for (int k = 0; k < 4; k++)
            vs[k] = g_full[(i + k < nflag) ? (i + k) : i];
        if (tid < 64) {
            int k = tid >> 4, j = tid & 15;
            s_z4[k][j] = reinterpret_cast<const float4*>(z + (size_t)vs[k] * DIM)[j];
        }
        __syncthreads();

        float lb[4] = {3.4e38f, 3.4e38f, 3.4e38f, 3.4e38f};
        int li[4] = {0, 0, 0, 0};
#pragma unroll
        for (int grp = 0; grp < 8; grp++) {
            float ac[4][4];
#pragma unroll
            for (int k = 0; k < 4; k++)
#pragma unroll
                for (int q = 0; q < 4; q++) ac[k][q] = 0.f;
            float4 e0 = g_eT4[0 * NC + grp * 1024 + 0 * 256 + tid];
            float4 e1 = g_eT4[0 * NC + grp * 1024 + 1 * 256 + tid];
            float4 e2 = g_eT4[0 * NC + grp * 1024 + 2 * 256 + tid];
            float4 e3 = g_eT4[0 * NC + grp * 1024 + 3 * 256 + tid];
#pragma unroll
            for (int jg = 0; jg < 16; jg++) {
                float4 n0, n1, n2, n3;
                if (jg < 15) {
                    n0 = g_eT4[(jg + 1) * NC + grp * 1024 + 0 * 256 + tid];
                    n1 = g_eT4[(jg + 1) * NC + grp * 1024 + 1 * 256 + tid];
                    n2 = g_eT4[(jg + 1) * NC + grp * 1024 + 2 * 256 + tid];
                    n3 = g_eT4[(jg + 1) * NC + grp * 1024 + 3 * 256 + tid];
                }
#pragma unroll
                for (int k = 0; k < 4; k++) {
                    float4 zj = s_z4[k][jg];
                    ac[k][0] = fmaf(zj.x, e0.x, ac[k][0]);
                    ac[k][0] = fmaf(zj.y, e0.y, ac[k][0]);
                    ac[k][0] = fmaf(zj.z, e0.z, ac[k][0]);
                    ac[k][0] = fmaf(zj.w, e0.w, ac[k][0]);
                    ac[k][1] = fmaf(zj.x, e1.x, ac[k][1]);
                    ac[k][1] = fmaf(zj.y, e1.y, ac[k][1]);
                    ac[k][1] = fmaf(zj.z, e1.z, ac[k][1]);
                    ac[k][1] = fmaf(zj.w, e1.w, ac[k][1]);
                    ac[k][2] = fmaf(zj.x, e2.x, ac[k][2]);
                    ac[k][2] = fmaf(zj.y, e2.y, ac[k][2]);
                    ac[k][2] = fmaf(zj.z, e2.z, ac[k][2]);
                    ac[k][2] = fmaf(zj.w, e2.w, ac[k][2]);
                    ac[k][3] = fmaf(zj.x, e3.x, ac[k][3]);
                    ac[k][3] = fmaf(zj.y, e3.y, ac[k][3]);
                    ac[k][3] = fmaf(zj.z, e3.z, ac[k][3]);
                    ac[k][3] = fmaf(zj.w, e3.w, ac[k][3]);
                }
                if (jg < 15) { e0 = n0; e1 = n1; e2 = n2; e3 = n3; }
            }
#pragma unroll
            for (int q = 0; q < 4; q++) {
                const int c = grp * 1024 + q * 256 + tid;
                const float es = g_esq[c];
#pragma unroll
                for (int k = 0; k < 4; k++) {
                    float s = fmaf(-2.f, ac[k][q], es);
                    if (s < lb[k]) { lb[k] = s; li[k] = c; }
                }
            }
        }
#pragma unroll
        for (int k = 0; k < 4; k++) { s_v[k][tid] = lb[k]; s_ix[k][tid] = li[k]; }
        __syncthreads();
#pragma unroll
        for (int o = 128; o > 0; o >>= 1) {
            if (tid < o) {
#pragma unroll
                for (int k = 0; k < 4; k++) {
                    float ov = s_v[k][tid + o];
                    int oi = s_ix[k][tid + o];
                    if (ov < s_v[k][tid] || (ov == s_v[k][tid] && oi < s_ix[k][tid])) {
                        s_v[k][tid] = ov;
                        s_ix[k][tid] = oi;
                    }
                }
            }
            __syncthreads();
        }
        if (tid < 4 && i + tid < nflag) g_bidx[vs[tid]] = s_ix[tid][0];
        __syncthreads();
    }
}

// ---------------- gather / ST / loss + fused final reduction (last block) ----------------
__global__ void __launch_bounds__(256) quant_kernel(const float* __restrict__ z,
                                                    const float* __restrict__ emb,
                                                    float* __restrict__ out) {
    __shared__ float s_red[256];
    __shared__ int s_last;
    const int tid = threadIdx.x;
    const int vl = tid >> 2, seg = tid & 3;
    const int v = blockIdx.x * 64 + vl;
    const int idx = g_bidx[v];

    const float4* zp = reinterpret_cast<const float4*>(z + (size_t)v * DIM) + seg * 4;
    const float4* qp = reinterpret_cast<const float4*>(emb + (size_t)idx * DIM) + seg * 4;
    float4* qo = reinterpret_cast<float4*>(out + (size_t)v * DIM) + seg * 4;
    float lsum = 0.f;
#pragma unroll
    for (int i = 0; i < 4; i++) {
        float4 zv = zp[i], q = qp[i];
        float dx = q.x - zv.x, dy = q.y - zv.y, dz = q.z - zv.z, dw = q.w - zv.w;
        qo[i] = make_float4(zv.x + dx, zv.y + dy, zv.z + dz, zv.w + dw);
        lsum += dx * dx + dy * dy + dz * dz + dw * dw;
    }
    if (seg == 0) out[OFF_IDX + v] = (float)idx;

    lsum += __shfl_down_sync(0xffffffffu, lsum, 2);
    lsum += __shfl_down_sync(0xffffffffu, lsum, 1);
    if (seg == 0) s_red[vl] = lsum;
    __syncthreads();
#pragma unroll
    for (int o = 32; o > 0; o >>= 1) {
        if (tid < o) s_red[tid] += s_red[tid + o];
        __syncthreads();
    }
    if (tid == 0) {
        g_partial[blockIdx.x] = s_red[0];
        __threadfence();
        s_last = (atomicAdd(&g_qticket, 1) == QBLOCKS - 1);
    }
    __syncthreads();
    if (!s_last) return;

    // last block: deterministic fixed-order tree over all partials
    s_red[tid] = g_partial[tid] + g_partial[tid + 256];
    __syncthreads();
#pragma unroll
    for (int o = 128; o > 0; o >>= 1) {
        if (tid < o) s_red[tid] += s_red[tid + o];
        __syncthreads();
    }
    if (tid == 0) {
        float loss = s_red[0] / (float)Q_ELEMS;
        out[OFF_VQ] = loss;
        out[OFF_COMMIT] = loss;
    }
}

// ---------------- launch ----------------
extern "C" void kernel_launch(void* const* d_in, const int* in_sizes, int n_in,
                              void* d_out, int out_size) {
    const float* z = (const float*)d_in[0];
    const float* emb = (const float*)d_in[1];
    if (n_in >= 2 && in_sizes[0] < in_sizes[1]) {
        const float* t = z; z = emb; emb = t;
    }
    float* out = (float*)d_out;

    cudaFuncSetAttribute(vq_mma_kernel,
                         cudaFuncAttributeMaxDynamicSharedMemorySize, DYN_SMEM);

    prep_emb_kernel<<<(NC + 255) / 256, 256>>>(emb);
    vq_mma_kernel<<<M_BLOCKS, 256, DYN_SMEM>>>(z);
    fixup_kernel<<<1024, 256>>>(z, emb);
    quant_kernel<<<QBLOCKS, 256>>>(z, emb, out);
}

// round 15
// speedup vs baseline: 1.1487x; 1.1487x over previous
#include <cuda_runtime.h>
#include <cuda_fp16.h>
#include <cstdint>

// ---------------- problem constants ----------------
#define NV 32768
#define NC 8192
#define DIM 64
#define Q_ELEMS (NV * DIM)
#define OFF_VQ Q_ELEMS
#define OFF_COMMIT (Q_ELEMS + 1)
#define OFF_IDX (Q_ELEMS + 2)

#define KP_BYTES 144
#define TILE_M 128
#define TILE_N 64
#define NT (NC / TILE_N)        // 128
#define M_BLOCKS (NV / TILE_M)  // 256
#define TAU 0.15f               // ~23-sigma statistical cover of fp16 score error

#define SM_A 0
#define SM_B 18432
#define SM_BSTRIDE 9472
#define SM_ESQ_OFF 9216
#define DYN_SMEM (18432 + 3 * 9472)

#define QBLOCKS (NV / 64)       // 512

// ---------------- device scratch ----------------
__device__ __align__(16) __half g_eh[NC * DIM];
__device__ __align__(16) float4 g_eT4[16 * NC];
__device__ __align__(16) float g_esq[NC];
__device__ int g_bidx[NV];
__device__ int3 g_pair[NV];
__device__ int g_full[NV];
__device__ int g_npair;
__device__ int g_nfull;
__device__ float g_partial[QBLOCKS];
__device__ int g_qticket;

// ---------------- PTX helpers ----------------
__device__ __forceinline__ uint32_t smem_u32(const void* p) {
    uint32_t a;
    asm("{ .reg .u64 t; cvta.to.shared.u64 t, %1; cvt.u32.u64 %0, t; }" : "=r"(a) : "l"(p));
    return a;
}
__device__ __forceinline__ void cpa16(uint32_t dst, const void* src) {
    asm volatile("cp.async.cg.shared.global [%0], [%1], 16;" :: "r"(dst), "l"(src));
}
#define CP_COMMIT() asm volatile("cp.async.commit_group;" ::: "memory")
#define CP_WAIT(n) asm volatile("cp.async.wait_group %0;" :: "n"(n) : "memory")

__device__ __forceinline__ void ldsm4(uint32_t& r0, uint32_t& r1, uint32_t& r2,
                                      uint32_t& r3, uint32_t addr) {
    asm volatile("ldmatrix.sync.aligned.m8n8.x4.shared.b16 {%0,%1,%2,%3}, [%4];"
                 : "=r"(r0), "=r"(r1), "=r"(r2), "=r"(r3) : "r"(addr));
}
__device__ __forceinline__ void mma16816(float* c, const uint32_t* a, uint32_t b0,
                                         uint32_t b1) {
    asm volatile(
        "mma.sync.aligned.m16n8k16.row.col.f32.f16.f16.f32 "
        "{%0,%1,%2,%3}, {%4,%5,%6,%7}, {%8,%9}, {%0,%1,%2,%3};"
        : "+f"(c[0]), "+f"(c[1]), "+f"(c[2]), "+f"(c[3])
        : "r"(a[0]), "r"(a[1]), "r"(a[2]), "r"(a[3]), "r"(b0), "r"(b1));
}

__device__ __forceinline__ void merge3(float& b1, float& b2, float& b3, int& i1, int& i2,
                                       float c1, float c2, float c3, int j1, int j2) {
    if (c1 < b1 || (c1 == b1 && j1 < i1)) {
        float t; int ti;
        t = b1; b1 = c1; c1 = t; ti = i1; i1 = j1; j1 = ti;
        t = b2; b2 = c2; c2 = t; ti = i2; i2 = j2; j2 = ti;
        t = b3; b3 = c3; c3 = t;
    }
    if (c1 < b2 || (c1 == b2 && j1 < i2)) {
        b3 = fminf(b2, c2);
        b2 = c1; i2 = j1;
    } else {
        b3 = fminf(b3, c1);
    }
}

// ---------------- prep: codebook ----------------
__global__ void prep_emb_kernel(const float* __restrict__ emb) {
    int c = blockIdx.x * blockDim.x + threadIdx.x;
    if (c == 0) { g_npair = 0; g_nfull = 0; g_qticket = 0; }
    if (c >= NC) return;
    const float4* row = reinterpret_cast<const float4*>(emb + (size_t)c * DIM);
    __half2* dst = reinterpret_cast<__half2*>(g_eh + (size_t)c * DIM);
    float s = 0.f;
#pragma unroll
    for (int i = 0; i < 16; i++) {
        float4 v = row[i];
        s += v.x * v.x + v.y * v.y + v.z * v.z + v.w * v.w;
        dst[2 * i] = __halves2half2(__float2half_rn(v.x), __float2half_rn(v.y));
        dst[2 * i + 1] = __halves2half2(__float2half_rn(v.z), __float2half_rn(v.w));
        g_eT4[i * NC + c] = v;
    }
    g_esq[c] = s;
}

// ---------------- main: HMMA distance GEMM + top-3 argmin (frozen since R9) ----------------
__global__ void __launch_bounds__(256, 2) vq_mma_kernel(const float* __restrict__ z) {
    extern __shared__ __align__(16) char dsm[];
    __shared__ float s_b[2][TILE_M], s_b2[2][TILE_M], s_b3[2][TILE_M];
    __shared__ int s_i[2][TILE_M], s_i2[2][TILE_M];

    const int tid = threadIdx.x;
    const int lane = tid & 31, wid = tid >> 5;
    const int wm = wid & 3, wn = wid >> 2;
    const uint32_t sb = smem_u32(dsm);

    {
        const float4* asrc =
            reinterpret_cast<const float4*>(z + (size_t)blockIdx.x * TILE_M * DIM);
#pragma unroll
        for (int k = 0; k < 4; k++) {
            int ch = tid + k * 256;
            int r = ch >> 3, pc = ch & 7;
            float4 f0 = asrc[2 * ch], f1 = asrc[2 * ch + 1];
            __half2 h[4];
            h[0] = __floats2half2_rn(f0.x, f0.y);
            h[1] = __floats2half2_rn(f0.z, f0.w);
            h[2] = __floats2half2_rn(f1.x, f1.y);
            h[3] = __floats2half2_rn(f1.z, f1.w);
            *reinterpret_cast<uint4*>(dsm + SM_A + r * KP_BYTES + pc * 16) =
                *reinterpret_cast<uint4*>(h);
        }
    }

    auto loadB = [&](int t, int stg) {
        uint32_t Bs = sb + SM_B + stg * SM_BSTRIDE;
        const uint4* bsrc =
            reinterpret_cast<const uint4*>(g_eh + (size_t)t * TILE_N * DIM);
#pragma unroll
        for (int i = 0; i < 2; i++) {
            int ch = tid + i * 256;
            int r = ch >> 3, c = ch & 7;
            cpa16(Bs + r * KP_BYTES + c * 16, bsrc + ch);
        }
        if (tid < 16)
            cpa16(Bs + SM_ESQ_OFF + tid * 16,
                  reinterpret_cast<const uint4*>(g_esq + t * TILE_N) + tid);
    };
    loadB(0, 0);
    CP_COMMIT();
    loadB(1, 1);
    CP_COMMIT();

    float b1[4], b2[4], b3[4];
    int i1[4], i2[4];
#pragma unroll
    for (int s = 0; s < 4; s++) {
        b1[s] = 3.4e38f; b2[s] = 3.4e38f; b3[s] = 3.4e38f; i1[s] = 0; i2[s] = 0;
    }

    const uint32_t a_row = wm * 32 + (lane & 15);
    const uint32_t a_koff = (lane >> 4) * 8;
    const uint32_t b_row0 = wn * 32 + ((lane >> 4) * 8) + (lane & 7);
    const uint32_t b_koff = ((lane >> 3) & 1) * 8;
    const int nq = (lane & 3) * 2;

    int st = 0, st2 = 2;
    for (int t = 0; t < NT; t++) {
        if (t + 1 < NT) { CP_WAIT(1); }
        else            { CP_WAIT(0); }
        __syncthreads();
        if (t + 2 < NT) { loadB(t + 2, st2); CP_COMMIT(); }

        float acc[2][4][4];
#pragma unroll
        for (int mf = 0; mf < 2; mf++)
#pragma unroll
            for (int nf = 0; nf < 4; nf++)
#pragma unroll
                for (int e = 0; e < 4; e++) acc[mf][nf][e] = 0.f;

        const uint32_t Bs = sb + SM_B + st * SM_BSTRIDE;
#pragma unroll
        for (int ks = 0; ks < DIM / 16; ks++) {
            uint32_t a[2][4];
#pragma unroll
            for (int mf = 0; mf < 2; mf++)
                ldsm4(a[mf][0], a[mf][1], a[mf][2], a[mf][3],
                      sb + SM_A + (a_row + mf * 16) * KP_BYTES +
                          (ks * 16 + a_koff) * 2);
            uint32_t b[4][2];
#pragma unroll
            for (int nh = 0; nh < 2; nh++)
                ldsm4(b[2 * nh][0], b[2 * nh][1], b[2 * nh + 1][0], b[2 * nh + 1][1],
                      Bs + (b_row0 + nh * 16) * KP_BYTES + (ks * 16 + b_koff) * 2);
#pragma unroll
            for (int mf = 0; mf < 2; mf++)
#pragma unroll
                for (int nf = 0; nf < 4; nf++)
                    mma16816(acc[mf][nf], a[mf], b[nf][0], b[nf][1]);
        }

        const float* esq =
            reinterpret_cast<const float*>(dsm + SM_B + st * SM_BSTRIDE + SM_ESQ_OFF);
        float sc[4][8];
#pragma unroll
        for (int mf = 0; mf < 2; mf++) {
#pragma unroll
            for (int nf = 0; nf < 4; nf++) {
                const int n0 = wn * 32 + nf * 8 + nq;
                const float e0 = esq[n0], e1 = esq[n0 + 1];
#pragma unroll
                for (int h = 0; h < 2; h++) {
                    sc[mf * 2 + h][nf * 2 + 0] = fmaf(-2.f, acc[mf][nf][2 * h], e0);
                    sc[mf * 2 + h][nf * 2 + 1] = fmaf(-2.f, acc[mf][nf][2 * h + 1], e1);
                }
            }
        }
#pragma unroll
        for (int s = 0; s < 4; s++) {
            float m01 = fminf(sc[s][0], sc[s][1]);
            float m23 = fminf(sc[s][2], sc[s][3]);
            float m45 = fminf(sc[s][4], sc[s][5]);
            float m67 = fminf(sc[s][6], sc[s][7]);
            float tmin = fminf(fminf(m01, m23), fminf(m45, m67));
            if (tmin < b3[s]) {
#pragma unroll
                for (int k = 0; k < 8; k++) {
                    float v = sc[s][k];
                    int idx = t * TILE_N + wn * 32 + (k >> 1) * 8 + nq + (k & 1);
                    if (v < b1[s]) {
                        b3[s] = b2[s]; b2[s] = b1[s]; i2[s] = i1[s];
                        b1[s] = v; i1[s] = idx;
                    } else if (v < b2[s]) {
                        b3[s] = b2[s]; b2[s] = v; i2[s] = idx;
                    } else if (v < b3[s]) {
                        b3[s] = v;
                    }
                }
            }
        }
        st = (st == 2) ? 0 : st + 1;
        st2 = (st2 == 2) ? 0 : st2 + 1;
    }

#pragma unroll
    for (int o = 1; o < 4; o <<= 1) {
#pragma unroll
        for (int s = 0; s < 4; s++) {
            float c1 = __shfl_xor_sync(0xffffffffu, b1[s], o);
            float c2 = __shfl_xor_sync(0xffffffffu, b2[s], o);
            float c3 = __shfl_xor_sync(0xffffffffu, b3[s], o);
            int j1 = __shfl_xor_sync(0xffffffffu, i1[s], o);
            int j2 = __shfl_xor_sync(0xffffffffu, i2[s], o);
            merge3(b1[s], b2[s], b3[s], i1[s], i2[s], c1, c2, c3, j1, j2);
        }
    }
    if ((lane & 3) == 0) {
#pragma unroll
        for (int s = 0; s < 4; s++) {
            int row = wm * 32 + (s >> 1) * 16 + (lane >> 2) + (s & 1) * 8;
            s_b[wn][row] = b1[s];
            s_b2[wn][row] = b2[s];
            s_b3[wn][row] = b3[s];
            s_i[wn][row] = i1[s];
            s_i2[wn][row] = i2[s];
        }
    }
    __syncthreads();
    if (tid < TILE_M) {
        float B1 = s_b[0][tid], B2 = s_b2[0][tid], B3 = s_b3[0][tid];
        int I1 = s_i[0][tid], I2 = s_i2[0][tid];
        merge3(B1, B2, B3, I1, I2,
               s_b[1][tid], s_b2[1][tid], s_b3[1][tid], s_i[1][tid], s_i2[1][tid]);
        const int v = blockIdx.x * TILE_M + tid;
        if (B2 - B1 >= TAU) {
            g_bidx[v] = I1;
        } else if (B3 - B1 >= TAU) {
            int p = atomicAdd(&g_npair, 1);
            g_pair[p] = make_int3(v, I1, I2);
        } else {
            int p = atomicAdd(&g_nfull, 1);
            g_full[p] = v;
        }
    }
}

// ---------------- combined fixup: pairs (threads) then full rescan (2 voxels/block) ----------------
__global__ void __launch_bounds__(256, 2) fixup_kernel(const float* __restrict__ z,
                                                       const float* __restrict__ emb) {
    // ---- phase 1: pair fixup, grid-stride over threads ----
    {
        const int n = g_npair;
        const int stride = gridDim.x * blockDim.x;
        for (int i = blockIdx.x * blockDim.x + threadIdx.x; i < n; i += stride) {
            int3 p = g_pair[i];
            const float4* zp = reinterpret_cast<const float4*>(z + (size_t)p.x * DIM);
            const float4* e1 = reinterpret_cast<const float4*>(emb + (size_t)p.y * DIM);
            const float4* e2 = reinterpret_cast<const float4*>(emb + (size_t)p.z * DIM);
            float d1 = 0.f, d2 = 0.f;
#pragma unroll
            for (int j = 0; j < 16; j++) {
                float4 zv = zp[j];
                float4 ea = e1[j], eb = e2[j];
                d1 = fmaf(zv.x, ea.x, d1); d1 = fmaf(zv.y, ea.y, d1);
                d1 = fmaf(zv.z, ea.z, d1); d1 = fmaf(zv.w, ea.w, d1);
                d2 = fmaf(zv.x, eb.x, d2); d2 = fmaf(zv.y, eb.y, d2);
                d2 = fmaf(zv.z, eb.z, d2); d2 = fmaf(zv.w, eb.w, d2);
            }
            float s1 = fmaf(-2.f, d1, g_esq[p.y]);
            float s2 = fmaf(-2.f, d2, g_esq[p.z]);
            int win;
            if (s1 < s2) win = p.y;
            else if (s2 < s1) win = p.z;
            else win = min(p.y, p.z);
            g_bidx[p.x] = win;
        }
    }

    // ---- phase 2: full rescan, 2 voxels per block (R13-proven, no spills) ----
    __shared__ __align__(16) float4 s_z4[2][16];
    __shared__ float s_v[2][256];
    __shared__ int s_ix[2][256];
    const int tid = threadIdx.x;
    const int nflag = g_nfull;

    for (int i = blockIdx.x * 2; i < nflag; i += gridDim.x * 2) {
        const int v0 = g_full[i];
        const bool has2 = (i + 1 < nflag);
        const int v1 = has2 ? g_full[i + 1] : v0;
        if (tid < 32) {
            int k = tid >> 4, j = tid & 15;
            int vv = k ? v1 : v0;
            s_z4[k][j] = reinterpret_cast<const float4*>(z + (size_t)vv * DIM)[j];
        }
        __syncthreads();

        float lb0 = 3.4e38f, lb1 = 3.4e38f;
        int li0 = 0, li1 = 0;
#pragma unroll
        for (int grp = 0; grp < 8; grp++) {
            float a0[4] = {0.f, 0.f, 0.f, 0.f};
            float a1[4] = {0.f, 0.f, 0.f, 0.f};
            float4 e0 = g_eT4[0 * NC + grp * 1024 + 0 * 256 + tid];
            float4 e1 = g_eT4[0 * NC + grp * 1024 + 1 * 256 + tid];
            float4 e2 = g_eT4[0 * NC + grp * 1024 + 2 * 256 + tid];
            float4 e3 = g_eT4[0 * NC + grp * 1024 + 3 * 256 + tid];
#pragma unroll
            for (int jg = 0; jg < 16; jg++) {
                float4 n0, n1, n2, n3;
                if (jg < 15) {
                    n0 = g_eT4[(jg + 1) * NC + grp * 1024 + 0 * 256 + tid];
                    n1 = g_eT4[(jg + 1) * NC + grp * 1024 + 1 * 256 + tid];
                    n2 = g_eT4[(jg + 1) * NC + grp * 1024 + 2 * 256 + tid];
                    n3 = g_eT4[(jg + 1) * NC + grp * 1024 + 3 * 256 + tid];
                }
                float4 za = s_z4[0][jg], zb = s_z4[1][jg];
                a0[0] = fmaf(za.x, e0.x, a0[0]); a0[0] = fmaf(za.y, e0.y, a0[0]);
                a0[0] = fmaf(za.z, e0.z, a0[0]); a0[0] = fmaf(za.w, e0.w, a0[0]);
                a0[1] = fmaf(za.x, e1.x, a0[1]); a0[1] = fmaf(za.y, e1.y, a0[1]);
                a0[1] = fmaf(za.z, e1.z, a0[1]); a0[1] = fmaf(za.w, e1.w, a0[1]);
                a0[2] = fmaf(za.x, e2.x, a0[2]); a0[2] = fmaf(za.y, e2.y, a0[2]);
                a0[2] = fmaf(za.z, e2.z, a0[2]); a0[2] = fmaf(za.w, e2.w, a0[2]);
                a0[3] = fmaf(za.x, e3.x, a0[3]); a0[3] = fmaf(za.y, e3.y, a0[3]);
                a0[3] = fmaf(za.z, e3.z, a0[3]); a0[3] = fmaf(za.w, e3.w, a0[3]);
                a1[0] = fmaf(zb.x, e0.x, a1[0]); a1[0] = fmaf(zb.y, e0.y, a1[0]);
                a1[0] = fmaf(zb.z, e0.z, a1[0]); a1[0] = fmaf(zb.w, e0.w, a1[0]);
                a1[1] = fmaf(zb.x, e1.x, a1[1]); a1[1] = fmaf(zb.y, e1.y, a1[1]);
                a1[1] = fmaf(zb.z, e1.z, a1[1]); a1[1] = fmaf(zb.w, e1.w, a1[1]);
                a1[2] = fmaf(zb.x, e2.x, a1[2]); a1[2] = fmaf(zb.y, e2.y, a1[2]);
                a1[2] = fmaf(zb.z, e2.z, a1[2]); a1[2] = fmaf(zb.w, e2.w, a1[2]);
                a1[3] = fmaf(zb.x, e3.x, a1[3]); a1[3] = fmaf(zb.y, e3.y, a1[3]);
                a1[3] = fmaf(zb.z, e3.z, a1[3]); a1[3] = fmaf(zb.w, e3.w, a1[3]);
                if (jg < 15) { e0 = n0; e1 = n1; e2 = n2; e3 = n3; }
            }
#pragma unroll
            for (int q = 0; q < 4; q++) {
                const int c = grp * 1024 + q * 256 + tid;
                const float es = g_esq[c];
                float s0 = fmaf(-2.f, a0[q], es);
                float s1 = fmaf(-2.f, a1[q], es);
                if (s0 < lb0) { lb0 = s0; li0 = c; }
                if (s1 < lb1) { lb1 = s1; li1 = c; }
            }
        }
        s_v[0][tid] = lb0; s_ix[0][tid] = li0;
        s_v[1][tid] = lb1; s_ix[1][tid] = li1;
        __syncthreads();
#pragma unroll
        for (int o = 128; o > 0; o >>= 1) {
            if (tid < o) {
#pragma unroll
                for (int k = 0; k < 2; k++) {
                    float ov = s_v[k][tid + o];
                    int oi = s_ix[k][tid + o];
                    if (ov < s_v[k][tid] || (ov == s_v[k][tid] && oi < s_ix[k][tid])) {
                        s_v[k][tid] = ov;
                        s_ix[k][tid] = oi;
                    }
                }
            }
            __syncthreads();
        }
        if (tid == 0) g_bidx[v0] = s_ix[0][0];
        if (tid == 1 && has2) g_bidx[v1] = s_ix[1][0];
        __syncthreads();
    }
}

// ---------------- gather / ST / loss + fused final reduction (last block) ----------------
__global__ void __launch_bounds__(256) quant_kernel(const float* __restrict__ z,
                                                    const float* __restrict__ emb,
                                                    float* __restrict__ out) {
    __shared__ float s_red[256];
    __shared__ int s_last;
    const int tid = threadIdx.x;
    const int vl = tid >> 2, seg = tid & 3;
    const int v = blockIdx.x * 64 + vl;
    const int idx = g_bidx[v];

    const float4* zp = reinterpret_cast<const float4*>(z + (size_t)v * DIM) + seg * 4;
    const float4* qp = reinterpret_cast<const float4*>(emb + (size_t)idx * DIM) + seg * 4;
    float4* qo = reinterpret_cast<float4*>(out + (size_t)v * DIM) + seg * 4;
    float lsum = 0.f;
#pragma unroll
    for (int i = 0; i < 4; i++) {
        float4 zv = zp[i], q = qp[i];
        float dx = q.x - zv.x, dy = q.y - zv.y, dz = q.z - zv.z, dw = q.w - zv.w;
        qo[i] = make_float4(zv.x + dx, zv.y + dy, zv.z + dz, zv.w + dw);
        lsum += dx * dx + dy * dy + dz * dz + dw * dw;
    }
    if (seg == 0) out[OFF_IDX + v] = (float)idx;

    lsum += __shfl_down_sync(0xffffffffu, lsum, 2);
    lsum += __shfl_down_sync(0xffffffffu, lsum, 1);
    if (seg == 0) s_red[vl] = lsum;
    __syncthreads();
#pragma unroll
    for (int o = 32; o > 0; o >>= 1) {
        if (tid < o) s_red[tid] += s_red[tid + o];
        __syncthreads();
    }
    if (tid == 0) {
        g_partial[blockIdx.x] = s_red[0];
        __threadfence();
        s_last = (atomicAdd(&g_qticket, 1) == QBLOCKS - 1);
    }
    __syncthreads();
    if (!s_last) return;

    // last block: deterministic fixed-order tree over all partials
    s_red[tid] = g_partial[tid] + g_partial[tid + 256];
    __syncthreads();
#pragma unroll
    for (int o = 128; o > 0; o >>= 1) {
        if (tid < o) s_red[tid] += s_red[tid + o];
        __syncthreads();
    }
    if (tid == 0) {
        float loss = s_red[0] / (float)Q_ELEMS;
        out[OFF_VQ] = loss;
        out[OFF_COMMIT] = loss;
    }
}

// ---------------- launch ----------------
extern "C" void kernel_launch(void* const* d_in, const int* in_sizes, int n_in,
                              void* d_out, int out_size) {
    const float* z = (const float*)d_in[0];
    const float* emb = (const float*)d_in[1];
    if (n_in >= 2 && in_sizes[0] < in_sizes[1]) {
        const float* t = z; z = emb; emb = t;
    }
    float* out = (float*)d_out;

    cudaFuncSetAttribute(vq_mma_kernel,
                         cudaFuncAttributeMaxDynamicSharedMemorySize, DYN_SMEM);

    prep_emb_kernel<<<(NC + 255) / 256, 256>>>(emb);
    vq_mma_kernel<<<M_BLOCKS, 256, DYN_SMEM>>>(z);
    fixup_kernel<<<1024, 256>>>(z, emb);
    quant_kernel<<<QBLOCKS, 256>>>(z, emb, out);
}

// round 16
// speedup vs baseline: 1.2079x; 1.0516x over previous
#include <cuda_runtime.h>
#include <cuda_fp16.h>
#include <cstdint>

// ---------------- problem constants ----------------
#define NV 32768
#define NC 8192
#define DIM 64
#define Q_ELEMS (NV * DIM)
#define OFF_VQ Q_ELEMS
#define OFF_COMMIT (Q_ELEMS + 1)
#define OFF_IDX (Q_ELEMS + 2)

#define KP_BYTES 144
#define TILE_M 128
#define TILE_N2 128                 // codes per B stage (two 64-code halves)
#define NT (NC / TILE_N2)           // 64 tiles
#define M_BLOCKS (NV / TILE_M)      // 256
#define TAU 0.15f                   // ~23-sigma statistical cover of fp16 score error

// smem: A 128*144=18432 | 3 B stages (128*144=18432 B-tile + 512 esq = 18944)
#define SM_A 0
#define SM_B 18432
#define SM_BSTRIDE 18944
#define SM_ESQ_OFF 18432
#define DYN_SMEM (18432 + 3 * 18944)

#define QBLOCKS (NV / 64)           // 512

// ---------------- device scratch ----------------
__device__ __align__(16) __half g_eh[NC * DIM];
__device__ __align__(16) float4 g_eT4[16 * NC];
__device__ __align__(16) float g_esq[NC];
__device__ int g_bidx[NV];
__device__ int3 g_pair[NV];
__device__ int g_full[NV];
__device__ int g_npair;
__device__ int g_nfull;
__device__ float g_partial[QBLOCKS];
__device__ int g_qticket;

// ---------------- PTX helpers ----------------
__device__ __forceinline__ uint32_t smem_u32(const void* p) {
    uint32_t a;
    asm("{ .reg .u64 t; cvta.to.shared.u64 t, %1; cvt.u32.u64 %0, t; }" : "=r"(a) : "l"(p));
    return a;
}
__device__ __forceinline__ void cpa16(uint32_t dst, const void* src) {
    asm volatile("cp.async.cg.shared.global [%0], [%1], 16;" :: "r"(dst), "l"(src));
}
#define CP_COMMIT() asm volatile("cp.async.commit_group;" ::: "memory")
#define CP_WAIT(n) asm volatile("cp.async.wait_group %0;" :: "n"(n) : "memory")

__device__ __forceinline__ void ldsm4(uint32_t& r0, uint32_t& r1, uint32_t& r2,
                                      uint32_t& r3, uint32_t addr) {
    asm volatile("ldmatrix.sync.aligned.m8n8.x4.shared.b16 {%0,%1,%2,%3}, [%4];"
                 : "=r"(r0), "=r"(r1), "=r"(r2), "=r"(r3) : "r"(addr));
}
__device__ __forceinline__ void mma16816(float* c, const uint32_t* a, uint32_t b0,
                                         uint32_t b1) {
    asm volatile(
        "mma.sync.aligned.m16n8k16.row.col.f32.f16.f16.f32 "
        "{%0,%1,%2,%3}, {%4,%5,%6,%7}, {%8,%9}, {%0,%1,%2,%3};"
        : "+f"(c[0]), "+f"(c[1]), "+f"(c[2]), "+f"(c[3])
        : "r"(a[0]), "r"(a[1]), "r"(a[2]), "r"(a[3]), "r"(b0), "r"(b1));
}

__device__ __forceinline__ void merge3(float& b1, float& b2, float& b3, int& i1, int& i2,
                                       float c1, float c2, float c3, int j1, int j2) {
    if (c1 < b1 || (c1 == b1 && j1 < i1)) {
        float t; int ti;
        t = b1; b1 = c1; c1 = t; ti = i1; i1 = j1; j1 = ti;
        t = b2; b2 = c2; c2 = t; ti = i2; i2 = j2; j2 = ti;
        t = b3; b3 = c3; c3 = t;
    }
    if (c1 < b2 || (c1 == b2 && j1 < i2)) {
        b3 = fminf(b2, c2);
        b2 = c1; i2 = j1;
    } else {
        b3 = fminf(b3, c1);
    }
}

// ---------------- prep: codebook ----------------
__global__ void prep_emb_kernel(const float* __restrict__ emb) {
    int c = blockIdx.x * blockDim.x + threadIdx.x;
    if (c == 0) { g_npair = 0; g_nfull = 0; g_qticket = 0; }
    if (c >= NC) return;
    const float4* row = reinterpret_cast<const float4*>(emb + (size_t)c * DIM);
    __half2* dst = reinterpret_cast<__half2*>(g_eh + (size_t)c * DIM);
    float s = 0.f;
#pragma unroll
    for (int i = 0; i < 16; i++) {
        float4 v = row[i];
        s += v.x * v.x + v.y * v.y + v.z * v.z + v.w * v.w;
        dst[2 * i] = __halves2half2(__float2half_rn(v.x), __float2half_rn(v.y));
        dst[2 * i + 1] = __halves2half2(__float2half_rn(v.z), __float2half_rn(v.w));
        g_eT4[i * NC + c] = v;
    }
    g_esq[c] = s;
}

// ---------------- main: HMMA distance GEMM + top-3 argmin ----------------
// B stages now hold 128 codes; each stage processed as two sequential 64-code
// halves (same registers as the proven R9 loop, half the barriers/waits).
__global__ void __launch_bounds__(256, 2) vq_mma_kernel(const float* __restrict__ z) {
    extern __shared__ __align__(16) char dsm[];
    __shared__ float s_b[2][TILE_M], s_b2[2][TILE_M], s_b3[2][TILE_M];
    __shared__ int s_i[2][TILE_M], s_i2[2][TILE_M];

    const int tid = threadIdx.x;
    const int lane = tid & 31, wid = tid >> 5;
    const int wm = wid & 3, wn = wid >> 2;
    const uint32_t sb = smem_u32(dsm);

    // A tile: fp32 z -> fp16 smem in-kernel (1024 dst chunks of 16B)
    {
        const float4* asrc =
            reinterpret_cast<const float4*>(z + (size_t)blockIdx.x * TILE_M * DIM);
#pragma unroll
        for (int k = 0; k < 4; k++) {
            int ch = tid + k * 256;
            int r = ch >> 3, pc = ch & 7;
            float4 f0 = asrc[2 * ch], f1 = asrc[2 * ch + 1];
            __half2 h[4];
            h[0] = __floats2half2_rn(f0.x, f0.y);
            h[1] = __floats2half2_rn(f0.z, f0.w);
            h[2] = __floats2half2_rn(f1.x, f1.y);
            h[3] = __floats2half2_rn(f1.z, f1.w);
            *reinterpret_cast<uint4*>(dsm + SM_A + r * KP_BYTES + pc * 16) =
                *reinterpret_cast<uint4*>(h);
        }
    }

    // B stage: 128 codes = 1024 chunks of 16B + 512B esq
    auto loadB = [&](int t, int stg) {
        uint32_t Bs = sb + SM_B + stg * SM_BSTRIDE;
        const uint4* bsrc =
            reinterpret_cast<const uint4*>(g_eh + (size_t)t * TILE_N2 * DIM);
#pragma unroll
        for (int i = 0; i < 4; i++) {
            int ch = tid + i * 256;
            int r = ch >> 3, c = ch & 7;
            cpa16(Bs + r * KP_BYTES + c * 16, bsrc + ch);
        }
        if (tid < 32)
            cpa16(Bs + SM_ESQ_OFF + tid * 16,
                  reinterpret_cast<const uint4*>(g_esq + t * TILE_N2) + tid);
    };
    loadB(0, 0);
    CP_COMMIT();
    loadB(1, 1);
    CP_COMMIT();

    float b1[4], b2[4], b3[4];
    int i1[4], i2[4];
#pragma unroll
    for (int s = 0; s < 4; s++) {
        b1[s] = 3.4e38f; b2[s] = 3.4e38f; b3[s] = 3.4e38f; i1[s] = 0; i2[s] = 0;
    }

    const uint32_t a_row = wm * 32 + (lane & 15);
    const uint32_t a_koff = (lane >> 4) * 8;
    const uint32_t b_row0 = wn * 32 + ((lane >> 4) * 8) + (lane & 7);
    const uint32_t b_koff = ((lane >> 3) & 1) * 8;
    const int nq = (lane & 3) * 2;

    int st = 0, st2 = 2;
    for (int t = 0; t < NT; t++) {
        if (t + 1 < NT) { CP_WAIT(1); }
        else            { CP_WAIT(0); }
        __syncthreads();
        if (t + 2 < NT) { loadB(t + 2, st2); CP_COMMIT(); }

        const uint32_t Bs = sb + SM_B + st * SM_BSTRIDE;
        const float* esq =
            reinterpret_cast<const float*>(dsm + SM_B + st * SM_BSTRIDE + SM_ESQ_OFF);

#pragma unroll
        for (int nh = 0; nh < 2; nh++) {
            float acc[2][4][4];
#pragma unroll
            for (int mf = 0; mf < 2; mf++)
#pragma unroll
                for (int nf = 0; nf < 4; nf++)
#pragma unroll
                    for (int e = 0; e < 4; e++) acc[mf][nf][e] = 0.f;

#pragma unroll
            for (int ks = 0; ks < DIM / 16; ks++) {
                uint32_t a[2][4];
#pragma unroll
                for (int mf = 0; mf < 2; mf++)
                    ldsm4(a[mf][0], a[mf][1], a[mf][2], a[mf][3],
                          sb + SM_A + (a_row + mf * 16) * KP_BYTES +
                              (ks * 16 + a_koff) * 2);
                uint32_t b[4][2];
#pragma unroll
                for (int nhh = 0; nhh < 2; nhh++)
                    ldsm4(b[2 * nhh][0], b[2 * nhh][1], b[2 * nhh + 1][0],
                          b[2 * nhh + 1][1],
                          Bs + (nh * 64 + b_row0 + nhh * 16) * KP_BYTES +
                              (ks * 16 + b_koff) * 2);
#pragma unroll
                for (int mf = 0; mf < 2; mf++)
#pragma unroll
                    for (int nf = 0; nf < 4; nf++)
                        mma16816(acc[mf][nf], a[mf], b[nf][0], b[nf][1]);
            }

            const float* esqh = esq + nh * 64;
            float sc[4][8];
#pragma unroll
            for (int mf = 0; mf < 2; mf++) {
#pragma unroll
                for (int nf = 0; nf < 4; nf++) {
                    const int n0 = wn * 32 + nf * 8 + nq;
                    const float e0 = esqh[n0], e1 = esqh[n0 + 1];
#pragma unroll
                    for (int h = 0; h < 2; h++) {
                        sc[mf * 2 + h][nf * 2 + 0] =
                            fmaf(-2.f, acc[mf][nf][2 * h], e0);
                        sc[mf * 2 + h][nf * 2 + 1] =
                            fmaf(-2.f, acc[mf][nf][2 * h + 1], e1);
                    }
                }
            }
#pragma unroll
            for (int s = 0; s < 4; s++) {
                float m01 = fminf(sc[s][0], sc[s][1]);
                float m23 = fminf(sc[s][2], sc[s][3]);
                float m45 = fminf(sc[s][4], sc[s][5]);
                float m67 = fminf(sc[s][6], sc[s][7]);
                float tmin = fminf(fminf(m01, m23), fminf(m45, m67));
                if (tmin < b3[s]) {
#pragma unroll
                    for (int k = 0; k < 8; k++) {
                        float v = sc[s][k];
                        int idx = t * TILE_N2 + nh * 64 + wn * 32 + (k >> 1) * 8 +
                                  nq + (k & 1);
                        if (v < b1[s]) {
                            b3[s] = b2[s]; b2[s] = b1[s]; i2[s] = i1[s];
                            b1[s] = v; i1[s] = idx;
                        } else if (v < b2[s]) {
                            b3[s] = b2[s]; b2[s] = v; i2[s] = idx;
                        } else if (v < b3[s]) {
                            b3[s] = v;
                        }
                    }
                }
            }
        }
        st = (st == 2) ? 0 : st + 1;
        st2 = (st2 == 2) ? 0 : st2 + 1;
    }

#pragma unroll
    for (int o = 1; o < 4; o <<= 1) {
#pragma unroll
        for (int s = 0; s < 4; s++) {
            float c1 = __shfl_xor_sync(0xffffffffu, b1[s], o);
            float c2 = __shfl_xor_sync(0xffffffffu, b2[s], o);
            float c3 = __shfl_xor_sync(0xffffffffu, b3[s], o);
            int j1 = __shfl_xor_sync(0xffffffffu, i1[s], o);
            int j2 = __shfl_xor_sync(0xffffffffu, i2[s], o);
            merge3(b1[s], b2[s], b3[s], i1[s], i2[s], c1, c2, c3, j1, j2);
        }
    }
    if ((lane & 3) == 0) {
#pragma unroll
        for (int s = 0; s < 4; s++) {
            int row = wm * 32 + (s >> 1) * 16 + (lane >> 2) + (s & 1) * 8;
            s_b[wn][row] = b1[s];
            s_b2[wn][row] = b2[s];
            s_b3[wn][row] = b3[s];
            s_i[wn][row] = i1[s];
            s_i2[wn][row] = i2[s];
        }
    }
    __syncthreads();
    if (tid < TILE_M) {
        float B1 = s_b[0][tid], B2 = s_b2[0][tid], B3 = s_b3[0][tid];
        int I1 = s_i[0][tid], I2 = s_i2[0][tid];
        merge3(B1, B2, B3, I1, I2,
               s_b[1][tid], s_b2[1][tid], s_b3[1][tid], s_i[1][tid], s_i2[1][tid]);
        const int v = blockIdx.x * TILE_M + tid;
        if (B2 - B1 >= TAU) {
            g_bidx[v] = I1;
        } else if (B3 - B1 >= TAU) {
            int p = atomicAdd(&g_npair, 1);
            g_pair[p] = make_int3(v, I1, I2);
        } else {
            int p = atomicAdd(&g_nfull, 1);
            g_full[p] = v;
        }
    }
}

// ---------------- combined fixup: pairs (threads) then full rescan (2 voxels/block) ----------------
__global__ void __launch_bounds__(256, 2) fixup_kernel(const float* __restrict__ z,
                                                       const float* __restrict__ emb) {
    // ---- phase 1: pair fixup ----
    {
        const int n = g_npair;
        const int stride = gridDim.x * blockDim.x;
        for (int i = blockIdx.x * blockDim.x + threadIdx.x; i < n; i += stride) {
            int3 p = g_pair[i];
            const float4* zp = reinterpret_cast<const float4*>(z + (size_t)p.x * DIM);
            const float4* e1 = reinterpret_cast<const float4*>(emb + (size_t)p.y * DIM);
            const float4* e2 = reinterpret_cast<const float4*>(emb + (size_t)p.z * DIM);
            float d1 = 0.f, d2 = 0.f;
#pragma unroll
            for (int j = 0; j < 16; j++) {
                float4 zv = zp[j];
                float4 ea = e1[j], eb = e2[j];
                d1 = fmaf(zv.x, ea.x, d1); d1 = fmaf(zv.y, ea.y, d1);
                d1 = fmaf(zv.z, ea.z, d1); d1 = fmaf(zv.w, ea.w, d1);
                d2 = fmaf(zv.x, eb.x, d2); d2 = fmaf(zv.y, eb.y, d2);
                d2 = fmaf(zv.z, eb.z, d2); d2 = fmaf(zv.w, eb.w, d2);
            }
            float s1 = fmaf(-2.f, d1, g_esq[p.y]);
            float s2 = fmaf(-2.f, d2, g_esq[p.z]);
            int win;
            if (s1 < s2) win = p.y;
            else if (s2 < s1) win = p.z;
            else win = min(p.y, p.z);
            g_bidx[p.x] = win;
        }
    }

    // ---- phase 2: full rescan, 2 voxels per block ----
    __shared__ __align__(16) float4 s_z4[2][16];
    __shared__ float s_v[2][256];
    __shared__ int s_ix[2][256];
    const int tid = threadIdx.x;
    const int nflag = g_nfull;

    for (int i = blockIdx.x * 2; i < nflag; i += gridDim.x * 2) {
        const int v0 = g_full[i];
        const bool has2 = (i + 1 < nflag);
        const int v1 = has2 ? g_full[i + 1] : v0;
        if (tid < 32) {
            int k = tid >> 4, j = tid & 15;
            int vv = k ? v1 : v0;
            s_z4[k][j] = reinterpret_cast<const float4*>(z + (size_t)vv * DIM)[j];
        }
        __syncthreads();

        float lb0 = 3.4e38f, lb1 = 3.4e38f;
        int li0 = 0, li1 = 0;
#pragma unroll
        for (int grp = 0; grp < 8; grp++) {
            float a0[4] = {0.f, 0.f, 0.f, 0.f};
            float a1[4] = {0.f, 0.f, 0.f, 0.f};
            float4 e0 = g_eT4[0 * NC + grp * 1024 + 0 * 256 + tid];
            float4 e1 = g_eT4[0 * NC + grp * 1024 + 1 * 256 + tid];
            float4 e2 = g_eT4[0 * NC + grp * 1024 + 2 * 256 + tid];
            float4 e3 = g_eT4[0 * NC + grp * 1024 + 3 * 256 + tid];
#pragma unroll
            for (int jg = 0; jg < 16; jg++) {
                float4 n0, n1, n2, n3;
                if (jg < 15) {
                    n0 = g_eT4[(jg + 1) * NC + grp * 1024 + 0 * 256 + tid];
                    n1 = g_eT4[(jg + 1) * NC + grp * 1024 + 1 * 256 + tid];
                    n2 = g_eT4[(jg + 1) * NC + grp * 1024 + 2 * 256 + tid];
                    n3 = g_eT4[(jg + 1) * NC + grp * 1024 + 3 * 256 + tid];
                }
                float4 za = s_z4[0][jg], zb = s_z4[1][jg];
                a0[0] = fmaf(za.x, e0.x, a0[0]); a0[0] = fmaf(za.y, e0.y, a0[0]);
                a0[0] = fmaf(za.z, e0.z, a0[0]); a0[0] = fmaf(za.w, e0.w, a0[0]);
                a0[1] = fmaf(za.x, e1.x, a0[1]); a0[1] = fmaf(za.y, e1.y, a0[1]);
                a0[1] = fmaf(za.z, e1.z, a0[1]); a0[1] = fmaf(za.w, e1.w, a0[1]);
                a0[2] = fmaf(za.x, e2.x, a0[2]); a0[2] = fmaf(za.y, e2.y, a0[2]);
                a0[2] = fmaf(za.z, e2.z, a0[2]); a0[2] = fmaf(za.w, e2.w, a0[2]);
                a0[3] = fmaf(za.x, e3.x, a0[3]); a0[3] = fmaf(za.y, e3.y, a0[3]);
                a0[3] = fmaf(za.z, e3.z, a0[3]); a0[3] = fmaf(za.w, e3.w, a0[3]);
                a1[0] = fmaf(zb.x, e0.x, a1[0]); a1[0] = fmaf(zb.y, e0.y, a1[0]);
                a1[0] = fmaf(zb.z, e0.z, a1[0]); a1[0] = fmaf(zb.w, e0.w, a1[0]);
                a1[1] = fmaf(zb.x, e1.x, a1[1]); a1[1] = fmaf(zb.y, e1.y, a1[1]);
                a1[1] = fmaf(zb.z, e1.z, a1[1]); a1[1] = fmaf(zb.w, e1.w, a1[1]);
                a1[2] = fmaf(zb.x, e2.x, a1[2]); a1[2] = fmaf(zb.y, e2.y, a1[2]);
                a1[2] = fmaf(zb.z, e2.z, a1[2]); a1[2] = fmaf(zb.w, e2.w, a1[2]);
                a1[3] = fmaf(zb.x, e3.x, a1[3]); a1[3] = fmaf(zb.y, e3.y, a1[3]);
                a1[3] = fmaf(zb.z, e3.z, a1[3]); a1[3] = fmaf(zb.w, e3.w, a1[3]);
                if (jg < 15) { e0 = n0; e1 = n1; e2 = n2; e3 = n3; }
            }
#pragma unroll
            for (int q = 0; q < 4; q++) {
                const int c = grp * 1024 + q * 256 + tid;
                const float es = g_esq[c];
                float s0 = fmaf(-2.f, a0[q], es);
                float s1 = fmaf(-2.f, a1[q], es);
                if (s0 < lb0) { lb0 = s0; li0 = c; }
                if (s1 < lb1) { lb1 = s1; li1 = c; }
            }
        }
        s_v[0][tid] = lb0; s_ix[0][tid] = li0;
        s_v[1][tid] = lb1; s_ix[1][tid] = li1;
        __syncthreads();
#pragma unroll
        for (int o = 128; o > 0; o >>= 1) {
            if (tid < o) {
#pragma unroll
                for (int k = 0; k < 2; k++) {
                    float ov = s_v[k][tid + o];
                    int oi = s_ix[k][tid + o];
                    if (ov < s_v[k][tid] || (ov == s_v[k][tid] && oi < s_ix[k][tid])) {
                        s_v[k][tid] = ov;
                        s_ix[k][tid] = oi;
                    }
                }
            }
            __syncthreads();
        }
        if (tid == 0) g_bidx[v0] = s_ix[0][0];
        if (tid == 1 && has2) g_bidx[v1] = s_ix[1][0];
        __syncthreads();
    }
}

// ---------------- gather / ST / loss + fused final reduction (last block) ----------------
__global__ void __launch_bounds__(256) quant_kernel(const float* __restrict__ z,
                                                    const float* __restrict__ emb,
                                                    float* __restrict__ out) {
    __shared__ float s_red[256];
    __shared__ int s_last;
    const int tid = threadIdx.x;
    const int vl = tid >> 2, seg = tid & 3;
    const int v = blockIdx.x * 64 + vl;
    const int idx = g_bidx[v];

    const float4* zp = reinterpret_cast<const float4*>(z + (size_t)v * DIM) + seg * 4;
    const float4* qp = reinterpret_cast<const float4*>(emb + (size_t)idx * DIM) + seg * 4;
    float4* qo = reinterpret_cast<float4*>(out + (size_t)v * DIM) + seg * 4;
    float lsum = 0.f;
#pragma unroll
    for (int i = 0; i < 4; i++) {
        float4 zv = zp[i], q = qp[i];
        float dx = q.x - zv.x, dy = q.y - zv.y, dz = q.z - zv.z, dw = q.w - zv.w;
        qo[i] = make_float4(zv.x + dx, zv.y + dy, zv.z + dz, zv.w + dw);
        lsum += dx * dx + dy * dy + dz * dz + dw * dw;
    }
    if (seg == 0) out[OFF_IDX + v] = (float)idx;

    lsum += __shfl_down_sync(0xffffffffu, lsum, 2);
    lsum += __shfl_down_sync(0xffffffffu, lsum, 1);
    if (seg == 0) s_red[vl] = lsum;
    __syncthreads();
#pragma unroll
    for (int o = 32; o > 0; o >>= 1) {
        if (tid < o) s_red[tid] += s_red[tid + o];
        __syncthreads();
    }
    if (tid == 0) {
        g_partial[blockIdx.x] = s_red[0];
        __threadfence();
        s_last = (atomicAdd(&g_qticket, 1) == QBLOCKS - 1);
    }
    __syncthreads();
    if (!s_last) return;

    s_red[tid] = g_partial[tid] + g_partial[tid + 256];
    __syncthreads();
#pragma unroll
    for (int o = 128; o > 0; o >>= 1) {
        if (tid < o) s_red[tid] += s_red[tid + o];
        __syncthreads();
    }
    if (tid == 0) {
        float loss = s_red[0] / (float)Q_ELEMS;
        out[OFF_VQ] = loss;
        out[OFF_COMMIT] = loss;
    }
}

// ---------------- launch ----------------
extern "C" void kernel_launch(void* const* d_in, const int* in_sizes, int n_in,
                              void* d_out, int out_size) {
    const float* z = (const float*)d_in[0];
    const float* emb = (const float*)d_in[1];
    if (n_in >= 2 && in_sizes[0] < in_sizes[1]) {
        const float* t = z; z = emb; emb = t;
    }
    float* out = (float*)d_out;

    cudaFuncSetAttribute(vq_mma_kernel,
                         cudaFuncAttributeMaxDynamicSharedMemorySize, DYN_SMEM);

    prep_emb_kernel<<<(NC + 255) / 256, 256>>>(emb);
    vq_mma_kernel<<<M_BLOCKS, 256, DYN_SMEM>>>(z);
    fixup_kernel<<<1024, 256>>>(z, emb);
    quant_kernel<<<QBLOCKS, 256>>>(z, emb, out);
}